// round 4
// baseline (speedup 1.0000x reference)
#include <cuda_runtime.h>

#define B_SZ 256
#define T_SZ 2000
#define F_SZ 128

#define CHUNK   80                 // timesteps per pipeline chunk
#define NCHUNK  (T_SZ / CHUNK)     // 25, exact
#define NBUF    4                  // ring depth (power of 2)
#define DOT_WARPS 8
#define T_PER_WARP (CHUNK / DOT_WARPS)  // 10
#define THREADS (32 * (DOT_WARPS + 1))  // 288: warp 0 = scan, warps 1..8 = dot

// BETA = sigmoid(2.0), VTH = 1.0
#define BETA_F 0.8807970779778823f

__global__ void __launch_bounds__(THREADS) lif_fused_kernel(
    const float* __restrict__ x, const float* __restrict__ W,
    const float* __restrict__ bias, float* __restrict__ out, int out_size)
{
    __shared__ float cur_s[NBUF][CHUNK];
    __shared__ int   full_cnt[NBUF];   // monotonic: +8 per produced chunk
    __shared__ int   freed;            // monotonic: chunks fully consumed

    const int b    = blockIdx.x;          // batch row
    const int wid  = threadIdx.x >> 5;
    const int lane = threadIdx.x & 31;

    if (threadIdx.x < NBUF) full_cnt[threadIdx.x] = 0;
    if (threadIdx.x == 0)   freed = 0;
    __syncthreads();

    volatile int* vfull  = full_cnt;
    volatile int* vfreed = &freed;

    const float* xrow = x + (size_t)b * T_SZ * F_SZ;

    if (wid > 0) {
        // ------------------ producer: dot warps ------------------
        const float4 wv = reinterpret_cast<const float4*>(W)[lane];
        const float  bias_v = bias[0];
        const int slice0 = (wid - 1) * T_PER_WARP;

        for (int c = 0; c < NCHUNK; ++c) {
            const int buf = c & (NBUF - 1);

            // wait until ring slot is free (scan has consumed chunk c-NBUF)
            if (c >= NBUF) {
                while (*vfreed < c - (NBUF - 1)) { }
            }
            __syncwarp();

            const int t0 = c * CHUNK + slice0;
            const float4* xp = reinterpret_cast<const float4*>(
                xrow + (size_t)t0 * F_SZ) + lane;

            // Phase 1: issue ALL loads (MLP=10) before dependent math
            float4 xv[T_PER_WARP];
            #pragma unroll
            for (int i = 0; i < T_PER_WARP; ++i)
                xv[i] = xp[i * (F_SZ / 4)];

            // Phase 2: reduce; shuffle latencies pipeline across rows
            #pragma unroll
            for (int i = 0; i < T_PER_WARP; ++i) {
                float s = xv[i].x * wv.x + xv[i].y * wv.y
                        + xv[i].z * wv.z + xv[i].w * wv.w;
                s += __shfl_xor_sync(0xFFFFFFFFu, s, 16);
                s += __shfl_xor_sync(0xFFFFFFFFu, s, 8);
                s += __shfl_xor_sync(0xFFFFFFFFu, s, 4);
                s += __shfl_xor_sync(0xFFFFFFFFu, s, 2);
                s += __shfl_xor_sync(0xFFFFFFFFu, s, 1);
                if (lane == 0)
                    cur_s[buf][slice0 + i] = s + bias_v;
            }

            __threadfence_block();     // slice visible before arrive
            if (lane == 0)
                atomicAdd(&full_cnt[buf], 1);
        }
    } else if (threadIdx.x == 0) {
        // ------------------ consumer: scan thread ------------------
        float v = 0.0f;
        float4 spk4;
        float* out_row = out + (size_t)b * T_SZ;

        int tgt[NBUF];
        #pragma unroll
        for (int i = 0; i < NBUF; ++i) tgt[i] = DOT_WARPS;

        for (int c = 0; c < NCHUNK; ++c) {
            const int buf = c & (NBUF - 1);

            while (vfull[buf] < tgt[buf]) { }
            tgt[buf] += DOT_WARPS;
            __threadfence_block();     // acquire: order data reads after spin

            const int tbase = c * CHUNK;
            #pragma unroll 4
            for (int tl = 0; tl < CHUNK; ++tl) {
                float cu = cur_s[buf][tl];
                float u  = fmaf(BETA_F, v, cu);    // leaky integrate
                float um = u - 1.0f;               // off critical path
                bool  p  = (u >= 1.0f);            // threshold (VTH=1)
                v = p ? um : u;                    // subtraction reset
                ((float*)&spk4)[tl & 3] = p ? 1.0f : 0.0f;
                if ((tl & 3) == 3)
                    reinterpret_cast<float4*>(out_row + tbase + (tl - 3))[0] = spk4;
            }

            __threadfence_block();     // reads done before releasing slot
            *vfreed = c + 1;
        }

        // final membrane potential vT
        if (out_size > B_SZ * T_SZ)
            out[B_SZ * T_SZ + b] = v;
    }
}

extern "C" void kernel_launch(void* const* d_in, const int* in_sizes, int n_in,
                              void* d_out, int out_size)
{
    const float* x    = (const float*)d_in[0];  // [256, 2000, 128] fp32
    const float* W    = (const float*)d_in[1];  // [128, 1] fp32
    const float* bias = (const float*)d_in[2];  // [1] fp32
    float* out = (float*)d_out;                 // spikes [256*2000] then vT [256]

    lif_fused_kernel<<<B_SZ, THREADS>>>(x, W, bias, out, out_size);
}

// round 5
// speedup vs baseline: 1.0623x; 1.0623x over previous
#include <cuda_runtime.h>

#define B_SZ 256
#define T_SZ 2000
#define F_SZ 128

#define CHUNK   80                 // timesteps per pipeline chunk
#define NCHUNK  (T_SZ / CHUNK)     // 25, exact
#define DOT_WARPS 8
#define T_PER_WARP (CHUNK / DOT_WARPS)  // 10
#define THREADS (32 * (DOT_WARPS + 1))  // 288: warp 0 = scan, warps 1..8 = dot

// BETA = sigmoid(2.0), VTH = 1.0
#define BETA_F 0.8807970779778823f

__global__ void __launch_bounds__(THREADS, 2) lif_fused_kernel(
    const float* __restrict__ x, const float* __restrict__ W,
    const float* __restrict__ bias, float* __restrict__ out, int out_size)
{
    __shared__ float cur_s[2][CHUNK];

    const int b    = blockIdx.x;          // batch row
    const int wid  = threadIdx.x >> 5;
    const int lane = threadIdx.x & 31;

    // ---- dot-warp state ----
    float4 wv;
    float  bias_v = 0.0f;
    float4 xv[T_PER_WARP];   // current chunk data
    float4 xn[T_PER_WARP];   // prefetched next chunk (in flight across barrier)
    const float4* xbase = nullptr;
    int slice0 = 0;

    if (wid > 0) {
        wv = reinterpret_cast<const float4*>(W)[lane];
        bias_v = bias[0];
        slice0 = (wid - 1) * T_PER_WARP;
        xbase = reinterpret_cast<const float4*>(
                    x + (size_t)b * T_SZ * F_SZ + (size_t)slice0 * F_SZ) + lane;

        // prologue: batch-load chunk 0
        #pragma unroll
        for (int i = 0; i < T_PER_WARP; ++i)
            xv[i] = xbase[i * (F_SZ / 4)];
    }

    // scan state (warp 0 lane 0 only)
    float v = 0.0f;
    float4 spk4;
    float* out_row = out + (size_t)b * T_SZ;

    for (int c = 0; c < NCHUNK; ++c) {
        const int buf = c & 1;

        if (wid > 0) {
            // Prefetch chunk c+1 (clamped) — issued BEFORE the reduce so these
            // loads stay in flight across the barrier and the scan phase.
            const int cn = (c + 1 < NCHUNK) ? c + 1 : c;
            const float4* xp = xbase + (size_t)cn * CHUNK * (F_SZ / 4);
            #pragma unroll
            for (int i = 0; i < T_PER_WARP; ++i)
                xn[i] = xp[i * (F_SZ / 4)];

            // Reduce current chunk; shuffle latencies pipeline across rows.
            #pragma unroll
            for (int i = 0; i < T_PER_WARP; ++i) {
                float s = xv[i].x * wv.x + xv[i].y * wv.y
                        + xv[i].z * wv.z + xv[i].w * wv.w;
                s += __shfl_xor_sync(0xFFFFFFFFu, s, 16);
                s += __shfl_xor_sync(0xFFFFFFFFu, s, 8);
                s += __shfl_xor_sync(0xFFFFFFFFu, s, 4);
                s += __shfl_xor_sync(0xFFFFFFFFu, s, 2);
                s += __shfl_xor_sync(0xFFFFFFFFu, s, 1);
                if (lane == 0)
                    cur_s[buf][slice0 + i] = s + bias_v;
            }
        }

        __syncthreads();   // chunk c dots visible; xn loads still in flight

        // Scan consumes chunk c while dot warps loop to iteration c+1 and
        // issue chunk c+2's prefetch, then reduce c+1 (already in flight).
        if (threadIdx.x == 0) {
            const int tbase = c * CHUNK;
            #pragma unroll 4
            for (int tl = 0; tl < CHUNK; ++tl) {
                float cu = cur_s[buf][tl];
                float u  = fmaf(BETA_F, v, cu);    // leaky integrate
                float um = u - 1.0f;               // off critical path
                bool  p  = (u >= 1.0f);            // threshold (VTH=1)
                v = p ? um : u;                    // subtraction reset
                ((float*)&spk4)[tl & 3] = p ? 1.0f : 0.0f;
                if ((tl & 3) == 3)
                    reinterpret_cast<float4*>(out_row + tbase + (tl - 3))[0] = spk4;
            }
        }

        if (wid > 0) {
            // rotate double buffer (renamed away under unroll)
            #pragma unroll
            for (int i = 0; i < T_PER_WARP; ++i)
                xv[i] = xn[i];
        }
    }

    // final membrane potential vT
    if (threadIdx.x == 0 && out_size > B_SZ * T_SZ)
        out[B_SZ * T_SZ + b] = v;
}

extern "C" void kernel_launch(void* const* d_in, const int* in_sizes, int n_in,
                              void* d_out, int out_size)
{
    const float* x    = (const float*)d_in[0];  // [256, 2000, 128] fp32
    const float* W    = (const float*)d_in[1];  // [128, 1] fp32
    const float* bias = (const float*)d_in[2];  // [1] fp32
    float* out = (float*)d_out;                 // spikes [256*2000] then vT [256]

    lif_fused_kernel<<<B_SZ, THREADS>>>(x, W, bias, out, out_size);
}

// round 6
// speedup vs baseline: 1.3512x; 1.2719x over previous
#include <cuda_runtime.h>

#define B_SZ 256
#define T_SZ 2000
#define F_SZ 128

#define CHUNK   80                 // timesteps per pipeline chunk
#define NCHUNK  (T_SZ / CHUNK)     // 25, exact
#define NBUF    4                  // smem ring depth
#define DOT_WARPS 8
#define T_PER_WARP (CHUNK / DOT_WARPS)  // 10
#define THREADS (32 * (DOT_WARPS + 1))  // 288: warp 0 = scan, warps 1..8 = dot

// BETA = sigmoid(2.0), VTH = 1.0
#define BETA_F 0.8807970779778823f

// named barriers: FULL(i) signals "buffer i produced", EMPTY(i) "buffer i free"
#define BAR_FULL(i)  (1 + (i))
#define BAR_EMPTY(i) (1 + NBUF + (i))

__device__ __forceinline__ void bar_sync(int id) {
    asm volatile("bar.sync %0, %1;" :: "r"(id), "n"(THREADS) : "memory");
}
__device__ __forceinline__ void bar_arrive(int id) {
    asm volatile("bar.arrive %0, %1;" :: "r"(id), "n"(THREADS) : "memory");
}

__global__ void __launch_bounds__(THREADS, 2) lif_fused_kernel(
    const float* __restrict__ x, const float* __restrict__ W,
    const float* __restrict__ bias, float* __restrict__ out, int out_size)
{
    __shared__ float cur_s[NBUF][CHUNK];

    const int b    = blockIdx.x;          // batch row
    const int wid  = threadIdx.x >> 5;
    const int lane = threadIdx.x & 31;

    if (wid > 0) {
        // ================= producers: dot warps 1..8 =================
        const float4 wv     = reinterpret_cast<const float4*>(W)[lane];
        const float  bias_v = bias[0];
        const int    slice0 = (wid - 1) * T_PER_WARP;
        const float4* xbase = reinterpret_cast<const float4*>(
            x + (size_t)b * T_SZ * F_SZ + (size_t)slice0 * F_SZ) + lane;

        for (int c = 0; c < NCHUNK; ++c) {
            const int buf = c & (NBUF - 1);

            // Phase 1: issue ALL loads for this chunk slice (registers only,
            // safe before the ring-slot wait; overlaps it).
            const float4* xp = xbase + (size_t)c * CHUNK * (F_SZ / 4);
            float4 xv[T_PER_WARP];
            #pragma unroll
            for (int i = 0; i < T_PER_WARP; ++i)
                xv[i] = xp[i * (F_SZ / 4)];

            // wait for ring slot to be free (consumer is <= NBUF behind)
            bar_sync(BAR_EMPTY(buf));

            // Phase 2: reduce each row; shuffle latencies pipeline across rows
            #pragma unroll
            for (int i = 0; i < T_PER_WARP; ++i) {
                float s = xv[i].x * wv.x + xv[i].y * wv.y
                        + xv[i].z * wv.z + xv[i].w * wv.w;
                s += __shfl_xor_sync(0xFFFFFFFFu, s, 16);
                s += __shfl_xor_sync(0xFFFFFFFFu, s, 8);
                s += __shfl_xor_sync(0xFFFFFFFFu, s, 4);
                s += __shfl_xor_sync(0xFFFFFFFFu, s, 2);
                s += __shfl_xor_sync(0xFFFFFFFFu, s, 1);
                if (lane == 0)
                    cur_s[buf][slice0 + i] = s + bias_v;
            }

            // signal buffer produced (non-blocking) and roll on
            bar_arrive(BAR_FULL(buf));
        }
    } else {
        // ================= consumer: scan warp 0 =================
        // prime all EMPTY barriers so producers can fill the whole ring
        #pragma unroll
        for (int i = 0; i < NBUF; ++i)
            bar_arrive(BAR_EMPTY(i));

        float v = 0.0f;
        float* out_row = out + (size_t)b * T_SZ;

        for (int c = 0; c < NCHUNK; ++c) {
            const int buf = c & (NBUF - 1);

            bar_sync(BAR_FULL(buf));   // wait for all 8 producer arrivals

            if (lane == 0) {
                const int tbase = c * CHUNK;
                #pragma unroll
                for (int g = 0; g < CHUNK / 4; ++g) {
                    float4 cu4 = reinterpret_cast<const float4*>(
                        &cur_s[buf][g * 4])[0];
                    float4 spk4;
                    #pragma unroll
                    for (int k = 0; k < 4; ++k) {
                        float cu = ((const float*)&cu4)[k];
                        float u  = fmaf(BETA_F, v, cu);   // leaky integrate
                        float um = u - 1.0f;              // off critical path
                        bool  p  = (u >= 1.0f);           // threshold (VTH=1)
                        v = p ? um : u;                   // subtraction reset
                        ((float*)&spk4)[k] = p ? 1.0f : 0.0f;
                    }
                    reinterpret_cast<float4*>(out_row + tbase + g * 4)[0] = spk4;
                }
            }

            bar_arrive(BAR_EMPTY(buf));  // release ring slot
        }

        // final membrane potential vT
        if (lane == 0 && out_size > B_SZ * T_SZ)
            out[B_SZ * T_SZ + b] = v;
    }
}

extern "C" void kernel_launch(void* const* d_in, const int* in_sizes, int n_in,
                              void* d_out, int out_size)
{
    const float* x    = (const float*)d_in[0];  // [256, 2000, 128] fp32
    const float* W    = (const float*)d_in[1];  // [128, 1] fp32
    const float* bias = (const float*)d_in[2];  // [1] fp32
    float* out = (float*)d_out;                 // spikes [256*2000] then vT [256]

    lif_fused_kernel<<<B_SZ, THREADS>>>(x, W, bias, out, out_size);
}